// round 5
// baseline (speedup 1.0000x reference)
#include <cuda_runtime.h>

#define B_   16
#define T_   512
#define C_   8
#define S_   64
#define KSZ_ 32
#define TOUT 481
#define EPSF 1e-8f

// Scratch (allocation-free rule: __device__ globals). g_xt padded +64 so the
// 3x float4 window loads at the t-edge stay in-bounds (values masked at store).
__device__ float g_xt[B_ * C_ * T_ + 64];          // x norm, transposed [b][ch][t]
// Broadcast-pair kernel: per (s,k,c) a float2 (-kn, -kn).  Viewed as ulonglong2
// pairs: knb[(s*32+k)*4 + i] = (qq_{2i}, qq_{2i+1}).  16B-aligned by type.
__device__ ulonglong2 g_knb[S_ * KSZ_ * 4];
// Half-sum-of-squares pairs: (q2/2, q2/2) per (s,k).
__device__ unsigned long long g_hq2[S_ * KSZ_];

// ---- packed f32x2 helpers (sm_100a) ---------------------------------------
__device__ __forceinline__ unsigned long long pk2(float lo, float hi) {
    unsigned long long r;
    asm("mov.b64 %0, {%1, %2};" : "=l"(r) : "f"(lo), "f"(hi));
    return r;
}
__device__ __forceinline__ unsigned long long fma2(unsigned long long a,
                                                   unsigned long long b,
                                                   unsigned long long c) {
    unsigned long long d;
    asm("fma.rn.f32x2 %0, %1, %2, %3;" : "=l"(d) : "l"(a), "l"(b), "l"(c));
    return d;
}
__device__ __forceinline__ unsigned long long mul2(unsigned long long a,
                                                   unsigned long long b) {
    unsigned long long d;
    asm("mul.rn.f32x2 %0, %1, %2;" : "=l"(d) : "l"(a), "l"(b));
    return d;
}
__device__ __forceinline__ void unpk2(unsigned long long v, float& lo, float& hi) {
    asm("mov.b64 {%0, %1}, %2;" : "=f"(lo), "=f"(hi) : "l"(v));
}

// ---------------------------------------------------------------------------
// Prep: blocks [0,128) normalize x per (b,ch) over T and transpose;
//       blocks [128,192) normalize kernel per s, store NEGATED broadcast
//       pairs (-kn,-kn) and (q2/2, q2/2) pairs.
// ---------------------------------------------------------------------------
__global__ __launch_bounds__(256) void lsd_prep(const float* __restrict__ x,
                                                const float* __restrict__ kern) {
    const int bid = blockIdx.x;
    const int tid = threadIdx.x;
    __shared__ float red0[256];
    __shared__ float red1[256];
    __shared__ float kns[256];

    if (bid < B_ * C_) {
        const int b = bid >> 3, ch = bid & 7;
        const float v0 = x[(b * T_ + tid) * C_ + ch];
        const float v1 = x[(b * T_ + tid + 256) * C_ + ch];
        red0[tid] = v0 + v1;
        red1[tid] = v0 * v0 + v1 * v1;
        __syncthreads();
        #pragma unroll
        for (int off = 128; off > 0; off >>= 1) {
            if (tid < off) { red0[tid] += red0[tid + off]; red1[tid] += red1[tid + off]; }
            __syncthreads();
        }
        const float mean = red0[0] * (1.0f / T_);
        const float var  = red1[0] * (1.0f / T_) - mean * mean;
        const float inv  = 1.0f / (sqrtf(fmaxf(var, 0.0f)) + EPSF);
        float* xr = &g_xt[(b * C_ + ch) * T_];
        xr[tid]       = (v0 - mean) * inv;
        xr[tid + 256] = (v1 - mean) * inv;
    } else {
        const int s = bid - B_ * C_;
        const float v = kern[s * 256 + tid];
        red0[tid] = v;
        red1[tid] = v * v;
        __syncthreads();
        #pragma unroll
        for (int off = 128; off > 0; off >>= 1) {
            if (tid < off) { red0[tid] += red0[tid + off]; red1[tid] += red1[tid + off]; }
            __syncthreads();
        }
        const float mean = red0[0] * (1.0f / 256.0f);
        const float var  = red1[0] * (1.0f / 256.0f) - mean * mean;
        const float inv  = 1.0f / (sqrtf(fmaxf(var, 0.0f)) + EPSF);
        const float kn = (v - mean) * inv;
        kns[tid] = kn;
        // broadcast pair, pre-negated: layout [s][k][c] as float2
        const int k = tid >> 3, c = tid & 7;
        ((float2*)g_knb)[(s * KSZ_ + k) * 8 + c] = make_float2(-kn, -kn);
        __syncthreads();
        if (tid < KSZ_) {
            float q2 = 0.0f;
            #pragma unroll
            for (int c2 = 0; c2 < 8; c2++) {
                const float t = kns[tid * 8 + c2];
                q2 = fmaf(t, t, q2);
            }
            const float h = 0.5f * q2;
            ((float2*)g_hq2)[s * KSZ_ + tid] = make_float2(h, h);
        }
    }
}

// ---------------------------------------------------------------------------
// Main: k WARP-UNIFORM (broadcast q loads), t across lanes.
//   grid = (64, 16):  blockIdx.y = b, blockIdx.x = tb*16 + kpair
//   block = 256 thr = 8 warps: warp w -> kk = w>>2 (k = kpair*2+kk), sg = w&3
//   lane l handles t = tb*128 + l*4 + j, j in [0,4), over s-quarter sg (16 s).
// Packed-across-j accumulators: acc_{j,j+1} = (q2/2 - dot_j, q2/2 - dot_{j+1})
// built from a[c] = (w[c],w[c+1]) and pre-negated qq pairs, init = hq2 pair.
// No scalar epilogue FMAs.  out = p2 + 2*min.
// ---------------------------------------------------------------------------
__global__ __launch_bounds__(256) void lsd_main(float* __restrict__ out) {
    const int tid = threadIdx.x;
    const int l   = tid & 31;
    const int w   = tid >> 5;
    const int kk  = w >> 2;                   // 0..1 (warp-uniform)
    const int sg  = w & 3;                    // 0..3 (warp-uniform)
    const int b   = blockIdx.y;
    const int tb  = blockIdx.x >> 4;          // 0..3
    const int kp  = blockIdx.x & 15;          // 0..15
    const int k   = kp * 2 + kk;              // warp-uniform
    const int ch  = k >> 2;
    const int m   = k & 3;

    const int t0     = tb * 128 + l * 4;
    const int wstart = t0 + 8 * m;            // multiple of 4 -> 16B aligned

    __shared__ float s_mn[3 * 256];

    // window: 12 floats via 3 aligned float4 loads (last unused)
    const float4* __restrict__ xv =
        (const float4*)(g_xt + (b * C_ + ch) * T_ + wstart);
    const float4 A = xv[0], Bv = xv[1], Cv = xv[2];
    float wv[11];
    wv[0] = A.x;  wv[1] = A.y;  wv[2] = A.z;  wv[3] = A.w;
    wv[4] = Bv.x; wv[5] = Bv.y; wv[6] = Bv.z; wv[7] = Bv.w;
    wv[8] = Cv.x; wv[9] = Cv.y; wv[10] = Cv.z;

    // packed sliding pairs a[i] = (w[i], w[i+1])
    unsigned long long a[10];
    #pragma unroll
    for (int i = 0; i < 10; i++) a[i] = pk2(wv[i], wv[i + 1]);

    float mn[4];
    #pragma unroll
    for (int j = 0; j < 4; j++) mn[j] = 3.4e38f;

    // warp-uniform base pointers for this warp's S-quarter
    const ulonglong2* __restrict__ knb = g_knb + (sg * 512 + k) * 4;
    const unsigned long long* __restrict__ hq2p = g_hq2 + sg * 512 + k;

    #pragma unroll
    for (int s = 0; s < 16; s++) {
        const ulonglong2 u0 = knb[s * 128];       // qq0, qq1 (negated)
        const ulonglong2 u1 = knb[s * 128 + 1];   // qq2, qq3
        const ulonglong2 u2 = knb[s * 128 + 2];   // qq4, qq5
        const ulonglong2 u3 = knb[s * 128 + 3];   // qq6, qq7
        const unsigned long long hq2 = hq2p[s * 32];

        // acc = (q2/2 - dot_j, q2/2 - dot_{j+1})
        unsigned long long accA = fma2(a[0], u0.x, hq2);
        unsigned long long accB = fma2(a[2], u0.x, hq2);
        accA = fma2(a[1], u0.y, accA);
        accB = fma2(a[3], u0.y, accB);
        accA = fma2(a[2], u1.x, accA);
        accB = fma2(a[4], u1.x, accB);
        accA = fma2(a[3], u1.y, accA);
        accB = fma2(a[5], u1.y, accB);
        accA = fma2(a[4], u2.x, accA);
        accB = fma2(a[6], u2.x, accB);
        accA = fma2(a[5], u2.y, accA);
        accB = fma2(a[7], u2.y, accB);
        accA = fma2(a[6], u3.x, accA);
        accB = fma2(a[8], u3.x, accB);
        accA = fma2(a[7], u3.y, accA);
        accB = fma2(a[9], u3.y, accB);

        float v0, v1, v2, v3;
        unpk2(accA, v0, v1);
        unpk2(accB, v2, v3);
        mn[0] = fminf(mn[0], v0);
        mn[1] = fminf(mn[1], v1);
        mn[2] = fminf(mn[2], v2);
        mn[3] = fminf(mn[3], v3);
    }

    // merge the four S-quarters (index within block: kk*128 + l*4 + j)
    if (sg >= 1) {
        #pragma unroll
        for (int j = 0; j < 4; j++)
            s_mn[(sg - 1) * 256 + kk * 128 + l * 4 + j] = mn[j];
    }
    __syncthreads();
    if (sg == 0) {
        // packed p2: (p2_0,p2_1) from a[0..7], (p2_2,p2_3) from a[2..9]
        unsigned long long pA = mul2(a[0], a[0]);
        unsigned long long pB = mul2(a[2], a[2]);
        #pragma unroll
        for (int c = 1; c < 8; c++) {
            pA = fma2(a[c], a[c], pA);
            pB = fma2(a[c + 2], a[c + 2], pB);
        }
        float p2j[4];
        unpk2(pA, p2j[0], p2j[1]);
        unpk2(pB, p2j[2], p2j[3]);

        #pragma unroll
        for (int j = 0; j < 4; j++) {
            const int t = t0 + j;
            if (t < TOUT) {
                const int base = kk * 128 + l * 4 + j;
                float v = mn[j];
                v = fminf(v, s_mn[0 * 256 + base]);
                v = fminf(v, s_mn[1 * 256 + base]);
                v = fminf(v, s_mn[2 * 256 + base]);
                out[(b * TOUT + t) * KSZ_ + k] = fmaf(2.0f, v, p2j[j]);
            }
        }
    }
}

extern "C" void kernel_launch(void* const* d_in, const int* in_sizes, int n_in,
                              void* d_out, int out_size) {
    const float* x    = (const float*)d_in[0];   // (16, 512, 8) f32
    const float* kern = (const float*)d_in[1];   // (64, 32, 8) f32
    float* out = (float*)d_out;                  // (16, 481, 32) f32

    lsd_prep<<<B_ * C_ + S_, 256>>>(x, kern);
    dim3 grid(64, B_);                           // (tb, kpair) x b
    lsd_main<<<grid, 256>>>(out);
}

// round 6
// speedup vs baseline: 1.4054x; 1.4054x over previous
#include <cuda_runtime.h>

#define B_   16
#define T_   512
#define C_   8
#define S_   64
#define KSZ_ 32
#define TOUT 481
#define EPSF 1e-8f

// Scratch (allocation-free rule: __device__ globals). g_xt padded +64 so the
// 3x float4 window loads at the t-edge stay in-bounds (values masked at store).
__device__ float g_xt[B_ * C_ * T_ + 64];          // x norm, transposed [b][ch][t]
// Broadcast-pair kernel: per (s,k,c) a float2 (-kn, -kn).  Viewed as ulonglong2
// pairs: knb[(s*32+k)*4 + i] = (qq_{2i}, qq_{2i+1}).
__device__ ulonglong2 g_knb[S_ * KSZ_ * 4];
// Half-sum-of-squares pairs: (q2/2, q2/2) per (s,k).
__device__ unsigned long long g_hq2[S_ * KSZ_];

// ---- packed f32x2 helpers (sm_100a) ---------------------------------------
__device__ __forceinline__ unsigned long long pk2(float lo, float hi) {
    unsigned long long r;
    asm("mov.b64 %0, {%1, %2};" : "=l"(r) : "f"(lo), "f"(hi));
    return r;
}
__device__ __forceinline__ unsigned long long fma2(unsigned long long a,
                                                   unsigned long long b,
                                                   unsigned long long c) {
    unsigned long long d;
    asm("fma.rn.f32x2 %0, %1, %2, %3;" : "=l"(d) : "l"(a), "l"(b), "l"(c));
    return d;
}
__device__ __forceinline__ unsigned long long mul2(unsigned long long a,
                                                   unsigned long long b) {
    unsigned long long d;
    asm("mul.rn.f32x2 %0, %1, %2;" : "=l"(d) : "l"(a), "l"(b));
    return d;
}
__device__ __forceinline__ void unpk2(unsigned long long v, float& lo, float& hi) {
    asm("mov.b64 {%0, %1}, %2;" : "=f"(lo), "=f"(hi) : "l"(v));
}

// ---------------------------------------------------------------------------
// Prep: blocks [0,128) normalize x per (b,ch) over T and transpose;
//       blocks [128,192) normalize kernel per s, store NEGATED broadcast
//       pairs (-kn,-kn) and (q2/2, q2/2) pairs.
// ---------------------------------------------------------------------------
__global__ __launch_bounds__(256) void lsd_prep(const float* __restrict__ x,
                                                const float* __restrict__ kern) {
    const int bid = blockIdx.x;
    const int tid = threadIdx.x;
    __shared__ float red0[256];
    __shared__ float red1[256];
    __shared__ float kns[256];

    if (bid < B_ * C_) {
        const int b = bid >> 3, ch = bid & 7;
        const float v0 = x[(b * T_ + tid) * C_ + ch];
        const float v1 = x[(b * T_ + tid + 256) * C_ + ch];
        red0[tid] = v0 + v1;
        red1[tid] = v0 * v0 + v1 * v1;
        __syncthreads();
        #pragma unroll
        for (int off = 128; off > 0; off >>= 1) {
            if (tid < off) { red0[tid] += red0[tid + off]; red1[tid] += red1[tid + off]; }
            __syncthreads();
        }
        const float mean = red0[0] * (1.0f / T_);
        const float var  = red1[0] * (1.0f / T_) - mean * mean;
        const float inv  = 1.0f / (sqrtf(fmaxf(var, 0.0f)) + EPSF);
        float* xr = &g_xt[(b * C_ + ch) * T_];
        xr[tid]       = (v0 - mean) * inv;
        xr[tid + 256] = (v1 - mean) * inv;
    } else {
        const int s = bid - B_ * C_;
        const float v = kern[s * 256 + tid];
        red0[tid] = v;
        red1[tid] = v * v;
        __syncthreads();
        #pragma unroll
        for (int off = 128; off > 0; off >>= 1) {
            if (tid < off) { red0[tid] += red0[tid + off]; red1[tid] += red1[tid + off]; }
            __syncthreads();
        }
        const float mean = red0[0] * (1.0f / 256.0f);
        const float var  = red1[0] * (1.0f / 256.0f) - mean * mean;
        const float inv  = 1.0f / (sqrtf(fmaxf(var, 0.0f)) + EPSF);
        const float kn = (v - mean) * inv;
        kns[tid] = kn;
        // broadcast pair, pre-negated: layout [s][k][c] as float2
        const int k = tid >> 3, c = tid & 7;
        ((float2*)g_knb)[(s * KSZ_ + k) * 8 + c] = make_float2(-kn, -kn);
        __syncthreads();
        if (tid < KSZ_) {
            float q2 = 0.0f;
            #pragma unroll
            for (int c2 = 0; c2 < 8; c2++) {
                const float t = kns[tid * 8 + c2];
                q2 = fmaf(t, t, q2);
            }
            const float h = 0.5f * q2;
            ((float2*)g_hq2)[s * KSZ_ + tid] = make_float2(h, h);
        }
    }
}

// ---------------------------------------------------------------------------
// Main: k WARP-UNIFORM, t across lanes. The block's q-slab (2 k x 64 s x
// 9 float2, padded to 10) is staged in smem once; the hot loop reads it via
// uniform-address LDS.128 (broadcast, conflict-free, fixed 29-cyc latency).
//   grid = (64, 16):  blockIdx.y = b, blockIdx.x = tb*16 + kpair
//   block = 256 thr = 8 warps: warp w -> kk = w>>2 (k = kpair*2+kk), sg = w&3
//   lane l handles t = tb*128 + l*4 + j, j in [0,4), over s-quarter sg (16 s).
// acc_{j,j+1} = (q2/2 - dot_j, q2/2 - dot_{j+1}); out = p2 + 2*min.
// __launch_bounds__(256,4): 64-reg budget so ptxas pipelines LDS across s.
// ---------------------------------------------------------------------------
__global__ __launch_bounds__(256, 4) void lsd_main(float* __restrict__ out) {
    const int tid = threadIdx.x;
    const int l   = tid & 31;
    const int w   = tid >> 5;
    const int kk  = w >> 2;                   // 0..1 (warp-uniform)
    const int sg  = w & 3;                    // 0..3 (warp-uniform)
    const int b   = blockIdx.y;
    const int tb  = blockIdx.x >> 4;          // 0..3
    const int kp  = blockIdx.x & 15;          // 0..15
    const int k   = kp * 2 + kk;              // warp-uniform
    const int ch  = k >> 2;
    const int m   = k & 3;

    // [kk][s] entry = 5 ulonglong2 (4 qq-pair vectors + hq2 + pad), 80B, aligned
    __shared__ ulonglong2 smq[2 * 64 * 5];
    __shared__ float s_mn[3 * 256];

    // ---- cooperative fill of smq (1152 float2 words over 256 threads) ----
    {
        const float2* __restrict__ knb2 = (const float2*)g_knb;
        const float2* __restrict__ hq22 = (const float2*)g_hq2;
        float2* smqf = (float2*)smq;
        #pragma unroll
        for (int it = 0; it < 5; it++) {
            const int idx = tid + it * 256;
            if (idx < 1152) {
                const int kkf = idx / 576;
                const int r   = idx - kkf * 576;
                const int s   = r / 9;
                const int e   = r - s * 9;
                const int kf  = kp * 2 + kkf;
                const float2 v = (e < 8) ? knb2[(s * KSZ_ + kf) * 8 + e]
                                         : hq22[s * KSZ_ + kf];
                smqf[(kkf * 64 + s) * 10 + e] = v;
            }
        }
    }

    // ---- window loads (overlap with smem fill) ----
    const int t0     = tb * 128 + l * 4;
    const int wstart = t0 + 8 * m;            // multiple of 4 -> 16B aligned
    const float4* __restrict__ xv =
        (const float4*)(g_xt + (b * C_ + ch) * T_ + wstart);
    const float4 A = xv[0], Bv = xv[1], Cv = xv[2];
    float wv[11];
    wv[0] = A.x;  wv[1] = A.y;  wv[2] = A.z;  wv[3] = A.w;
    wv[4] = Bv.x; wv[5] = Bv.y; wv[6] = Bv.z; wv[7] = Bv.w;
    wv[8] = Cv.x; wv[9] = Cv.y; wv[10] = Cv.z;

    unsigned long long a[10];
    #pragma unroll
    for (int i = 0; i < 10; i++) a[i] = pk2(wv[i], wv[i + 1]);

    __syncthreads();

    // warp-uniform smem base for this warp's S-quarter
    const ulonglong2* __restrict__ qv = smq + (kk * 64 + sg * 16) * 5;

    float mn[4];
    #pragma unroll
    for (int s = 0; s < 16; s++) {
        const ulonglong2 u0 = qv[s * 5 + 0];      // qq0, qq1 (negated)
        const ulonglong2 u1 = qv[s * 5 + 1];      // qq2, qq3
        const ulonglong2 u2 = qv[s * 5 + 2];      // qq4, qq5
        const ulonglong2 u3 = qv[s * 5 + 3];      // qq6, qq7
        const unsigned long long hq2 =
            *(const unsigned long long*)(qv + s * 5 + 4);

        unsigned long long accA = fma2(a[0], u0.x, hq2);
        unsigned long long accB = fma2(a[2], u0.x, hq2);
        accA = fma2(a[1], u0.y, accA);
        accB = fma2(a[3], u0.y, accB);
        accA = fma2(a[2], u1.x, accA);
        accB = fma2(a[4], u1.x, accB);
        accA = fma2(a[3], u1.y, accA);
        accB = fma2(a[5], u1.y, accB);
        accA = fma2(a[4], u2.x, accA);
        accB = fma2(a[6], u2.x, accB);
        accA = fma2(a[5], u2.y, accA);
        accB = fma2(a[7], u2.y, accB);
        accA = fma2(a[6], u3.x, accA);
        accB = fma2(a[8], u3.x, accB);
        accA = fma2(a[7], u3.y, accA);
        accB = fma2(a[9], u3.y, accB);

        float v0, v1, v2, v3;
        unpk2(accA, v0, v1);
        unpk2(accB, v2, v3);
        if (s == 0) {
            mn[0] = v0; mn[1] = v1; mn[2] = v2; mn[3] = v3;
        } else {
            mn[0] = fminf(mn[0], v0);
            mn[1] = fminf(mn[1], v1);
            mn[2] = fminf(mn[2], v2);
            mn[3] = fminf(mn[3], v3);
        }
    }

    // merge the four S-quarters (index within block: kk*128 + l*4 + j)
    if (sg >= 1) {
        #pragma unroll
        for (int j = 0; j < 4; j++)
            s_mn[(sg - 1) * 256 + kk * 128 + l * 4 + j] = mn[j];
    }
    __syncthreads();
    if (sg == 0) {
        // packed p2: (p2_0,p2_1) from a[0..7], (p2_2,p2_3) from a[2..9]
        unsigned long long pA = mul2(a[0], a[0]);
        unsigned long long pB = mul2(a[2], a[2]);
        #pragma unroll
        for (int c = 1; c < 8; c++) {
            pA = fma2(a[c], a[c], pA);
            pB = fma2(a[c + 2], a[c + 2], pB);
        }
        float p2j[4];
        unpk2(pA, p2j[0], p2j[1]);
        unpk2(pB, p2j[2], p2j[3]);

        #pragma unroll
        for (int j = 0; j < 4; j++) {
            const int t = t0 + j;
            if (t < TOUT) {
                const int base = kk * 128 + l * 4 + j;
                float v = mn[j];
                v = fminf(v, s_mn[0 * 256 + base]);
                v = fminf(v, s_mn[1 * 256 + base]);
                v = fminf(v, s_mn[2 * 256 + base]);
                out[(b * TOUT + t) * KSZ_ + k] = fmaf(2.0f, v, p2j[j]);
            }
        }
    }
}

extern "C" void kernel_launch(void* const* d_in, const int* in_sizes, int n_in,
                              void* d_out, int out_size) {
    const float* x    = (const float*)d_in[0];   // (16, 512, 8) f32
    const float* kern = (const float*)d_in[1];   // (64, 32, 8) f32
    float* out = (float*)d_out;                  // (16, 481, 32) f32

    lsd_prep<<<B_ * C_ + S_, 256>>>(x, kern);
    dim3 grid(64, B_);                           // (tb, kpair) x b
    lsd_main<<<grid, 256>>>(out);
}

// round 7
// speedup vs baseline: 1.4444x; 1.0278x over previous
#include <cuda_runtime.h>

#define B_   16
#define T_   512
#define C_   8
#define S_   64
#define KSZ_ 32
#define TOUT 481
#define EPSF 1e-8f

// Scratch (allocation-free rule: __device__ globals). g_xt padded +64 so the
// 3x float4 window loads at the t-edge stay in-bounds (values masked at store).
__device__ float g_xt[B_ * C_ * T_ + 64];   // x norm, transposed [b][ch][t]
// Kernel slab in FINAL per-k layout: [k][s][8 x float4] = 128B per (k,s) entry:
//   float2 e=0..7 : broadcast pairs (-kn,-kn) for c=0..7
//   float2 e=8    : (q2/2, q2/2)
//   e=9..15       : padding (never read)
// Main kernel copies its 2 k-slabs to smem with pure shift/mask indexing.
__device__ float4 g_slab[KSZ_ * S_ * 8];

// ---- packed f32x2 helpers (sm_100a) ---------------------------------------
__device__ __forceinline__ unsigned long long pk2(float lo, float hi) {
    unsigned long long r;
    asm("mov.b64 %0, {%1, %2};" : "=l"(r) : "f"(lo), "f"(hi));
    return r;
}
__device__ __forceinline__ unsigned long long fma2(unsigned long long a,
                                                   unsigned long long b,
                                                   unsigned long long c) {
    unsigned long long d;
    asm("fma.rn.f32x2 %0, %1, %2, %3;" : "=l"(d) : "l"(a), "l"(b), "l"(c));
    return d;
}
__device__ __forceinline__ unsigned long long mul2(unsigned long long a,
                                                   unsigned long long b) {
    unsigned long long d;
    asm("mul.rn.f32x2 %0, %1, %2;" : "=l"(d) : "l"(a), "l"(b));
    return d;
}
__device__ __forceinline__ void unpk2(unsigned long long v, float& lo, float& hi) {
    asm("mov.b64 {%0, %1}, %2;" : "=f"(lo), "=f"(hi) : "l"(v));
}

// ---------------------------------------------------------------------------
// Prep: blocks [0,128) normalize x per (b,ch) over T and transpose;
//       blocks [128,192) normalize kernel per s, writing the padded slab
//       layout (negated broadcast pairs + hq2).
// ---------------------------------------------------------------------------
__global__ __launch_bounds__(256) void lsd_prep(const float* __restrict__ x,
                                                const float* __restrict__ kern) {
    const int bid = blockIdx.x;
    const int tid = threadIdx.x;
    __shared__ float red0[256];
    __shared__ float red1[256];
    __shared__ float kns[256];

    if (bid < B_ * C_) {
        const int b = bid >> 3, ch = bid & 7;
        const float v0 = x[(b * T_ + tid) * C_ + ch];
        const float v1 = x[(b * T_ + tid + 256) * C_ + ch];
        red0[tid] = v0 + v1;
        red1[tid] = v0 * v0 + v1 * v1;
        __syncthreads();
        #pragma unroll
        for (int off = 128; off > 0; off >>= 1) {
            if (tid < off) { red0[tid] += red0[tid + off]; red1[tid] += red1[tid + off]; }
            __syncthreads();
        }
        const float mean = red0[0] * (1.0f / T_);
        const float var  = red1[0] * (1.0f / T_) - mean * mean;
        const float inv  = 1.0f / (sqrtf(fmaxf(var, 0.0f)) + EPSF);
        float* xr = &g_xt[(b * C_ + ch) * T_];
        xr[tid]       = (v0 - mean) * inv;
        xr[tid + 256] = (v1 - mean) * inv;
    } else {
        const int s = bid - B_ * C_;
        const float v = kern[s * 256 + tid];
        red0[tid] = v;
        red1[tid] = v * v;
        __syncthreads();
        #pragma unroll
        for (int off = 128; off > 0; off >>= 1) {
            if (tid < off) { red0[tid] += red0[tid + off]; red1[tid] += red1[tid + off]; }
            __syncthreads();
        }
        const float mean = red0[0] * (1.0f / 256.0f);
        const float var  = red1[0] * (1.0f / 256.0f) - mean * mean;
        const float inv  = 1.0f / (sqrtf(fmaxf(var, 0.0f)) + EPSF);
        const float kn = (v - mean) * inv;
        kns[tid] = kn;
        // slab entry [k][s], float2 element c: (-kn, -kn)
        const int k = tid >> 3, c = tid & 7;
        ((float2*)g_slab)[(k * S_ + s) * 16 + c] = make_float2(-kn, -kn);
        __syncthreads();
        if (tid < KSZ_) {
            float q2 = 0.0f;
            #pragma unroll
            for (int c2 = 0; c2 < 8; c2++) {
                const float t = kns[tid * 8 + c2];
                q2 = fmaf(t, t, q2);
            }
            const float h = 0.5f * q2;
            ((float2*)g_slab)[(tid * S_ + s) * 16 + 8] = make_float2(h, h);
        }
    }
}

// ---------------------------------------------------------------------------
// Main: k WARP-UNIFORM, t across lanes. The block's two k-slabs (2 x 64 s x
// 128B) are copied to smem with pure shift/mask indexing; the hot loop reads
// them via uniform-address LDS (broadcast, fixed latency).
//   grid = (64, 16):  blockIdx.y = b, blockIdx.x = tb*16 + kpair
//   block = 256 thr = 8 warps: warp w -> kk = w>>2 (k = kpair*2+kk), sg = w&3
//   lane l handles t = tb*128 + l*4 + j, j in [0,4), over s-quarter sg (16 s).
// acc_{j,j+1} = (q2/2 - dot_j, q2/2 - dot_{j+1}); out = p2 + 2*min.
// __launch_bounds__(256,5): 51-reg budget -> 5 blocks/SM (62.5% occ cap).
// ---------------------------------------------------------------------------
__global__ __launch_bounds__(256, 5) void lsd_main(float* __restrict__ out) {
    const int tid = threadIdx.x;
    const int l   = tid & 31;
    const int w   = tid >> 5;
    const int kk  = w >> 2;                   // 0..1 (warp-uniform)
    const int sg  = w & 3;                    // 0..3 (warp-uniform)
    const int b   = blockIdx.y;
    const int tb  = blockIdx.x >> 4;          // 0..3
    const int kp  = blockIdx.x & 15;          // 0..15
    const int k   = kp * 2 + kk;              // warp-uniform
    const int ch  = k >> 2;
    const int m   = k & 3;

    __shared__ float4 smq4[2 * 64 * 8];       // 16KB: [kk][s][8 float4]
    __shared__ float s_mn[3 * 256];

    // ---- slab copy: 1024 float4, pure shift/mask indexing ----
    {
        const float4* __restrict__ gsl = g_slab;
        #pragma unroll
        for (int it = 0; it < 4; it++) {
            const int idx = tid + it * 256;
            const int kkf = idx >> 9;         // 0..1
            const int rest = idx & 511;
            smq4[idx] = gsl[(kp * 2 + kkf) * 512 + rest];
        }
    }

    // ---- window loads (overlap with smem fill) ----
    const int t0     = tb * 128 + l * 4;
    const int wstart = t0 + 8 * m;            // multiple of 4 -> 16B aligned
    const float4* __restrict__ xv =
        (const float4*)(g_xt + (b * C_ + ch) * T_ + wstart);
    const float4 A = xv[0], Bv = xv[1], Cv = xv[2];
    float wv[11];
    wv[0] = A.x;  wv[1] = A.y;  wv[2] = A.z;  wv[3] = A.w;
    wv[4] = Bv.x; wv[5] = Bv.y; wv[6] = Bv.z; wv[7] = Bv.w;
    wv[8] = Cv.x; wv[9] = Cv.y; wv[10] = Cv.z;

    unsigned long long a[10];
    #pragma unroll
    for (int i = 0; i < 10; i++) a[i] = pk2(wv[i], wv[i + 1]);

    __syncthreads();

    // warp-uniform smem base for this warp's S-quarter (16B units)
    const ulonglong2* __restrict__ qv =
        (const ulonglong2*)smq4 + (kk * 64 + sg * 16) * 8;

    float mn[4];
    #pragma unroll
    for (int s = 0; s < 16; s++) {
        const ulonglong2 u0 = qv[s * 8 + 0];      // qq0, qq1 (negated)
        const ulonglong2 u1 = qv[s * 8 + 1];      // qq2, qq3
        const ulonglong2 u2 = qv[s * 8 + 2];      // qq4, qq5
        const ulonglong2 u3 = qv[s * 8 + 3];      // qq6, qq7
        const unsigned long long hq2 =
            *(const unsigned long long*)(qv + s * 8 + 4);

        unsigned long long accA = fma2(a[0], u0.x, hq2);
        unsigned long long accB = fma2(a[2], u0.x, hq2);
        accA = fma2(a[1], u0.y, accA);
        accB = fma2(a[3], u0.y, accB);
        accA = fma2(a[2], u1.x, accA);
        accB = fma2(a[4], u1.x, accB);
        accA = fma2(a[3], u1.y, accA);
        accB = fma2(a[5], u1.y, accB);
        accA = fma2(a[4], u2.x, accA);
        accB = fma2(a[6], u2.x, accB);
        accA = fma2(a[5], u2.y, accA);
        accB = fma2(a[7], u2.y, accB);
        accA = fma2(a[6], u3.x, accA);
        accB = fma2(a[8], u3.x, accB);
        accA = fma2(a[7], u3.y, accA);
        accB = fma2(a[9], u3.y, accB);

        float v0, v1, v2, v3;
        unpk2(accA, v0, v1);
        unpk2(accB, v2, v3);
        if (s == 0) {
            mn[0] = v0; mn[1] = v1; mn[2] = v2; mn[3] = v3;
        } else {
            mn[0] = fminf(mn[0], v0);
            mn[1] = fminf(mn[1], v1);
            mn[2] = fminf(mn[2], v2);
            mn[3] = fminf(mn[3], v3);
        }
    }

    // merge the four S-quarters (index within block: kk*128 + l*4 + j)
    if (sg >= 1) {
        #pragma unroll
        for (int j = 0; j < 4; j++)
            s_mn[(sg - 1) * 256 + kk * 128 + l * 4 + j] = mn[j];
    }
    __syncthreads();
    if (sg == 0) {
        // packed p2: (p2_0,p2_1) from a[0..7], (p2_2,p2_3) from a[2..9]
        unsigned long long pA = mul2(a[0], a[0]);
        unsigned long long pB = mul2(a[2], a[2]);
        #pragma unroll
        for (int c = 1; c < 8; c++) {
            pA = fma2(a[c], a[c], pA);
            pB = fma2(a[c + 2], a[c + 2], pB);
        }
        float p2j[4];
        unpk2(pA, p2j[0], p2j[1]);
        unpk2(pB, p2j[2], p2j[3]);

        #pragma unroll
        for (int j = 0; j < 4; j++) {
            const int t = t0 + j;
            if (t < TOUT) {
                const int base = kk * 128 + l * 4 + j;
                float v = mn[j];
                v = fminf(v, s_mn[0 * 256 + base]);
                v = fminf(v, s_mn[1 * 256 + base]);
                v = fminf(v, s_mn[2 * 256 + base]);
                out[(b * TOUT + t) * KSZ_ + k] = fmaf(2.0f, v, p2j[j]);
            }
        }
    }
}

extern "C" void kernel_launch(void* const* d_in, const int* in_sizes, int n_in,
                              void* d_out, int out_size) {
    const float* x    = (const float*)d_in[0];   // (16, 512, 8) f32
    const float* kern = (const float*)d_in[1];   // (64, 32, 8) f32
    float* out = (float*)d_out;                  // (16, 481, 32) f32

    lsd_prep<<<B_ * C_ + S_, 256>>>(x, kern);
    dim3 grid(64, B_);                           // (tb, kpair) x b
    lsd_main<<<grid, 256>>>(out);
}